// round 10
// baseline (speedup 1.0000x reference)
#include <cuda_runtime.h>

// Problem constants (fixed by the dataset)
#define BB   16
#define NN   32
#define HH   512
#define WW   512
#define CC   512
#define SS   256    // 16*16 pooled spatial
#define EE   128

typedef unsigned long long ull;

// Scratch (static device globals — zero-initialized at load; the kernel
// restores the zeroed state before exit so graph replays stay deterministic).
__device__ float g_obj[BB * NN * EE];    // 256 KB: pooled numerators (REDG accum)
__device__ float g_mr[BB * NN * SS];     // resized masks [bn][s]
__device__ float g_minv[BB * NN];        // 1/(mask_sum + eps)
__device__ float g_w1T[EE * EE];         // w1 transposed [k][e]
__device__ float g_w2T[EE * EE];         // w2 transposed [k][e]
__device__ int   g_ctr;                  // mask+transpose blocks done (target 514)
__device__ int   g_done;                 // GEMM blocks done with obj atomics (128)
__device__ int   g_fin;                  // GEMM blocks fully done (last resets all)

// Packed f32x2 helpers (sm_103a dual-lane fp32 FMA; ptxas never auto-emits)
__device__ __forceinline__ ull dup2(float x) {
    ull r; unsigned u = __float_as_uint(x);
    asm("mov.b64 %0, {%1, %1};" : "=l"(r) : "r"(u));
    return r;
}
__device__ __forceinline__ void ffma2(ull& d, ull a, ull b) {
    asm("fma.rn.f32x2 %0, %1, %2, %0;" : "+l"(d) : "l"(a), "l"(b));
}
__device__ __forceinline__ float lo32(ull v) { return __uint_as_float((unsigned)v); }
__device__ __forceinline__ float hi32(ull v) { return __uint_as_float((unsigned)(v >> 32)); }

// Swizzled index into the 64x64 proj staging tile (quad rotation).
__device__ __forceinline__ int sp_idx(int ls, int e) {
    return ls * 64 + ((((e >> 2) + (ls >> 2)) & 15) << 2) + (e & 3);
}

#define SW(bf,k,e) sBuf[(bf)*1088 + (k)*68 + (e)]
#define SF(bf,k,s) sBuf[2176 + (bf)*1088 + (k)*68 + (s)]

// ---------------------------------------------------------------------------
// Single fused kernel (128 threads/block, grid 642):
//   blocks [0,128):   GEMM 64Ex64SxK512 (f32x2) + BN/ReLU + pooling GEMM2 ->
//                     REDG g_obj -> device barrier -> per-block 4-row MLP.
//   blocks [128,640): bilinear mask resize + sums -> g_ctr.
//   blocks 640,641:   transpose w1/w2 -> g_w1T/g_w2T -> g_ctr.
// ---------------------------------------------------------------------------
__global__ void __launch_bounds__(128) kernelA(
    const float* __restrict__ features,   // [B, C, 16, 16]
    const float* __restrict__ masks,      // [B, N, 512, 512]
    const float* __restrict__ conv_w,     // [E, C]
    const float* __restrict__ conv_b,
    const float* __restrict__ bn_gamma, const float* __restrict__ bn_beta,
    const float* __restrict__ bn_mean,  const float* __restrict__ bn_var,
    const float* __restrict__ w1, const float* __restrict__ w2,
    const float* __restrict__ b1, const float* __restrict__ b2,
    float* __restrict__ out)
{
    __shared__ float sBuf[4352];          // sW/sF buffers -> sP tile -> MLP xs/hs
    __shared__ float smr[NN][64];         // mask tile [n][local s]
    __shared__ float red[4];

    const int blk = blockIdx.x;
    const int tid = threadIdx.x;

    if (blk >= 640) {
        // ---------------- weight transpose path (aliases sBuf) -------------
        float (*ttile)[33] = (float (*)[33])sBuf;
        const float* src = (blk == 640) ? w1 : w2;
        float* dstT      = (blk == 640) ? g_w1T : g_w2T;
        const int rr = tid >> 5;
        const int cc = tid & 31;
        for (int t = 0; t < 16; t++) {
            const int ti = t >> 2, tj = t & 3;
            #pragma unroll
            for (int rs = 0; rs < 8; rs++) {
                const int row = rs * 4 + rr;
                ttile[row][cc] = src[(size_t)(ti * 32 + row) * EE + tj * 32 + cc];
            }
            __syncthreads();
            #pragma unroll
            for (int rs = 0; rs < 8; rs++) {
                const int row = rs * 4 + rr;
                dstT[(size_t)(tj * 32 + row) * EE + ti * 32 + cc] = ttile[cc][row];
            }
            __syncthreads();
        }
        __threadfence();
        if (tid == 0) atomicAdd(&g_ctr, 1);
        return;
    }

    if (blk >= 128) {
        // ---------------- mask resize path ----------------
        const int bn = blk - 128;                 // 0..511
        const float* m = masks + (size_t)bn * (HH * WW);
        float lsum = 0.0f;

        #pragma unroll
        for (int rep = 0; rep < 2; rep++) {
            const int t = tid + rep * 128;        // pooled pixel 0..255
            const int o = t >> 4;
            const int p = t & 15;
            float sy = (o + 0.5f) * ((float)HH / 16.0f) - 0.5f;
            sy = fmaxf(sy, 0.0f);
            int   y0 = (int)floorf(sy);
            float fy = sy - (float)y0;
            int   y1 = min(y0 + 1, HH - 1);
            float sx = (p + 0.5f) * ((float)WW / 16.0f) - 0.5f;
            sx = fmaxf(sx, 0.0f);
            int   x0 = (int)floorf(sx);
            float fx = sx - (float)x0;
            int   x1 = min(x0 + 1, WW - 1);

            float v00 = m[(size_t)y0 * WW + x0];
            float v01 = m[(size_t)y0 * WW + x1];
            float v10 = m[(size_t)y1 * WW + x0];
            float v11 = m[(size_t)y1 * WW + x1];
            float v = (1.0f - fy) * ((1.0f - fx) * v00 + fx * v01)
                    +          fy * ((1.0f - fx) * v10 + fx * v11);

            g_mr[(size_t)bn * SS + t] = v;
            lsum += v;
        }
        __threadfence();   // publish g_mr stores before the flag
        #pragma unroll
        for (int off = 16; off > 0; off >>= 1)
            lsum += __shfl_xor_sync(0xFFFFFFFFu, lsum, off);
        if ((tid & 31) == 0) red[tid >> 5] = lsum;
        __syncthreads();
        if (tid == 0) {
            g_minv[bn] = 1.0f / (red[0] + red[1] + red[2] + red[3] + 1e-8f);
            __threadfence();
            atomicAdd(&g_ctr, 1);
        }
        return;
    }

    // ---------------- GEMM path ----------------
    const int et    = blk >> 6;           // 0..1  (E tile of 64)
    const int stile = blk & 63;           // 0..63
    const int b     = stile >> 2;
    const int s0    = (stile & 3) * 64;
    const int eBase = et * 64;

    const int te = tid >> 4;              // 0..7  -> e micro-row = te*8
    const int ts = tid & 15;              // 0..15 -> s micro-col = ts*4

    // W load: coalesced row segments, transposed on smem store
    const int wq  = tid & 3;
    const int wei = tid >> 2;             // 0..31 (rows wei, wei+32)
    const float* wp = conv_w + (size_t)(eBase + wei) * CC + (wq << 2);

    // F load: [k][s] coalesced
    const int fk  = tid >> 4;             // 0..7
    const int fsq = (tid & 15) << 2;
    const float* fp = features + ((size_t)b * CC + fk) * SS + s0 + fsq;

    // packed accumulators: acc[j][i] = s-col j, e-pair i (e = te*8 + 2i, 2i+1)
    ull acc[4][4];
    #pragma unroll
    for (int j = 0; j < 4; j++)
        #pragma unroll
        for (int i = 0; i < 4; i++) acc[j][i] = 0ull;

    float4 wr0 = *(const float4*)wp;
    float4 wr1 = *(const float4*)(wp + 32 * CC);
    float4 fr0 = *(const float4*)fp;
    float4 fr1 = *(const float4*)(fp + 8 * SS);

    {
        const int kk = wq << 2;
        SW(0, kk + 0, wei) = wr0.x;  SW(0, kk + 0, wei + 32) = wr1.x;
        SW(0, kk + 1, wei) = wr0.y;  SW(0, kk + 1, wei + 32) = wr1.y;
        SW(0, kk + 2, wei) = wr0.z;  SW(0, kk + 2, wei + 32) = wr1.z;
        SW(0, kk + 3, wei) = wr0.w;  SW(0, kk + 3, wei + 32) = wr1.w;
        *(float4*)&SF(0, fk, fsq)     = fr0;
        *(float4*)&SF(0, fk + 8, fsq) = fr1;
    }
    __syncthreads();

    #pragma unroll 1
    for (int t = 0; t < 32; t++) {
        const int cur = t & 1;
        if (t < 31) {
            const int c0 = (t + 1) << 4;
            wr0 = *(const float4*)(wp + c0);
            wr1 = *(const float4*)(wp + 32 * CC + c0);
            fr0 = *(const float4*)(fp + (size_t)c0 * SS);
            fr1 = *(const float4*)(fp + (size_t)(c0 + 8) * SS);
        }
        #pragma unroll
        for (int k = 0; k < 16; k++) {
            ulonglong2 A0 = *(const ulonglong2*)&SW(cur, k, te << 3);
            ulonglong2 A1 = *(const ulonglong2*)&SW(cur, k, (te << 3) + 4);
            float4 f = *(const float4*)&SF(cur, k, ts << 2);
            ull f0 = dup2(f.x), f1 = dup2(f.y), f2 = dup2(f.z), f3 = dup2(f.w);
            ffma2(acc[0][0], A0.x, f0); ffma2(acc[0][1], A0.y, f0);
            ffma2(acc[0][2], A1.x, f0); ffma2(acc[0][3], A1.y, f0);
            ffma2(acc[1][0], A0.x, f1); ffma2(acc[1][1], A0.y, f1);
            ffma2(acc[1][2], A1.x, f1); ffma2(acc[1][3], A1.y, f1);
            ffma2(acc[2][0], A0.x, f2); ffma2(acc[2][1], A0.y, f2);
            ffma2(acc[2][2], A1.x, f2); ffma2(acc[2][3], A1.y, f2);
            ffma2(acc[3][0], A0.x, f3); ffma2(acc[3][1], A0.y, f3);
            ffma2(acc[3][2], A1.x, f3); ffma2(acc[3][3], A1.y, f3);
        }
        if (t < 31) {
            const int nxt = cur ^ 1;
            const int kk = wq << 2;
            SW(nxt, kk + 0, wei) = wr0.x;  SW(nxt, kk + 0, wei + 32) = wr1.x;
            SW(nxt, kk + 1, wei) = wr0.y;  SW(nxt, kk + 1, wei + 32) = wr1.y;
            SW(nxt, kk + 2, wei) = wr0.z;  SW(nxt, kk + 2, wei + 32) = wr1.z;
            SW(nxt, kk + 3, wei) = wr0.w;  SW(nxt, kk + 3, wei + 32) = wr1.w;
            *(float4*)&SF(nxt, fk, fsq)     = fr0;
            *(float4*)&SF(nxt, fk + 8, fsq) = fr1;
        }
        __syncthreads();
    }

    // BN + ReLU in registers, then stage the proj tile into sBuf (swizzled).
    {
        float scv[8], bv[8];
        #pragma unroll
        for (int i = 0; i < 8; i++) {
            const int e = eBase + (te << 3) + i;
            scv[i] = bn_gamma[e] * rsqrtf(bn_var[e] + 1e-5f);
            bv[i]  = (conv_b[e] - bn_mean[e]) * scv[i] + bn_beta[e];
        }
        #pragma unroll
        for (int j = 0; j < 4; j++) {
            const int ls = (ts << 2) + j;
            float pv[8];
            #pragma unroll
            for (int i = 0; i < 4; i++) {
                pv[2 * i]     = lo32(acc[j][i]);
                pv[2 * i + 1] = hi32(acc[j][i]);
            }
            float4 o0, o1;
            o0.x = fmaxf(pv[0] * scv[0] + bv[0], 0.f);
            o0.y = fmaxf(pv[1] * scv[1] + bv[1], 0.f);
            o0.z = fmaxf(pv[2] * scv[2] + bv[2], 0.f);
            o0.w = fmaxf(pv[3] * scv[3] + bv[3], 0.f);
            o1.x = fmaxf(pv[4] * scv[4] + bv[4], 0.f);
            o1.y = fmaxf(pv[5] * scv[5] + bv[5], 0.f);
            o1.z = fmaxf(pv[6] * scv[6] + bv[6], 0.f);
            o1.w = fmaxf(pv[7] * scv[7] + bv[7], 0.f);
            *(float4*)&sBuf[sp_idx(ls, (te << 3))]     = o0;
            *(float4*)&sBuf[sp_idx(ls, (te << 3) + 4)] = o1;
        }
    }

    // Wait for all mask + transpose blocks (they finish long before the K-loop).
    if (tid == 0) {
        while (*(volatile int*)&g_ctr < 514) __nanosleep(100);
    }
    __syncthreads();
    __threadfence();

    // Load this block's mask tile [32 n][64 s]
    for (int i = tid; i < NN * 64; i += 128)
        smr[i >> 6][i & 63] = g_mr[(size_t)(b * NN + (i >> 6)) * SS + s0 + (i & 63)];
    __syncthreads();

    // GEMM2: obj_partial[n][e] = sum_ls smr[n][ls] * proj[ls][e]
    {
        const int tn = tid >> 4;          // 0..7 -> n0 = 4*tn
        const int tc = tid & 15;          // e0 = 4*tc
        float ob[4][4];
        #pragma unroll
        for (int r = 0; r < 4; r++)
            #pragma unroll
            for (int c = 0; c < 4; c++) ob[r][c] = 0.f;

        #pragma unroll 4
        for (int ls = 0; ls < 64; ls++) {
            float4 pv = *(const float4*)&sBuf[sp_idx(ls, tc << 2)];
            #pragma unroll
            for (int r = 0; r < 4; r++) {
                const float m = smr[(tn << 2) + r][ls];
                ob[r][0] += m * pv.x;
                ob[r][1] += m * pv.y;
                ob[r][2] += m * pv.z;
                ob[r][3] += m * pv.w;
            }
        }
        #pragma unroll
        for (int r = 0; r < 4; r++) {
            float* dst = &g_obj[(size_t)(b * NN + (tn << 2) + r) * EE
                                + eBase + (tc << 2)];
            #pragma unroll
            for (int c = 0; c < 4; c++)
                atomicAdd(dst + c, ob[r][c]);
        }
    }

    // -------- device barrier: all GEMM blocks' obj atomics visible ---------
    __threadfence();
    __syncthreads();
    if (tid == 0) {
        atomicAdd(&g_done, 1);
        while (*(volatile int*)&g_done < 128) __nanosleep(100);
    }
    __syncthreads();
    __threadfence();

    // -------- MLP for this block's 4 (b,n) rows: rows bn0..bn0+3 ----------
    {
        float* xs = sBuf;                 // [4][132]
        float* hs = sBuf + 4 * 132;       // [4][132]
        const int bn0 = blk << 2;
        const int e = tid;

        #pragma unroll
        for (int r = 0; r < 4; r++) {
            const size_t idx = (size_t)(bn0 + r) * EE + e;
            xs[r * 132 + e] = g_obj[idx] * g_minv[bn0 + r];
            g_obj[idx] = 0.f;             // restore zeros for next graph replay
        }
        __syncthreads();

        // layer 1
        {
            float a0 = 0.f, a1 = 0.f, a2 = 0.f, a3 = 0.f;
            const float* wt = g_w1T + e;
            #pragma unroll 8
            for (int k = 0; k < EE; k++) {
                const float wv = wt[k << 7];
                a0 += wv * xs[0 * 132 + k];
                a1 += wv * xs[1 * 132 + k];
                a2 += wv * xs[2 * 132 + k];
                a3 += wv * xs[3 * 132 + k];
            }
            const float bb = b1[e];
            hs[0 * 132 + e] = fmaxf(a0 + bb, 0.f);
            hs[1 * 132 + e] = fmaxf(a1 + bb, 0.f);
            hs[2 * 132 + e] = fmaxf(a2 + bb, 0.f);
            hs[3 * 132 + e] = fmaxf(a3 + bb, 0.f);
        }
        __syncthreads();

        // layer 2
        {
            float a0 = 0.f, a1 = 0.f, a2 = 0.f, a3 = 0.f;
            const float* wt = g_w2T + e;
            #pragma unroll 8
            for (int k = 0; k < EE; k++) {
                const float wv = wt[k << 7];
                a0 += wv * hs[0 * 132 + k];
                a1 += wv * hs[1 * 132 + k];
                a2 += wv * hs[2 * 132 + k];
                a3 += wv * hs[3 * 132 + k];
            }
            const float bb = b2[e];
            out[(size_t)(bn0 + 0) * EE + e] = a0 + bb;
            out[(size_t)(bn0 + 1) * EE + e] = a1 + bb;
            out[(size_t)(bn0 + 2) * EE + e] = a2 + bb;
            out[(size_t)(bn0 + 3) * EE + e] = a3 + bb;
        }
    }

    // -------- last-one-out: reset counters for the next graph replay -------
    __syncthreads();
    if (tid == 0) {
        __threadfence();
        const int prev = atomicAdd(&g_fin, 1);
        if (prev == 127) {                // last GEMM block out
            g_ctr = 0;
            g_done = 0;
            g_fin = 0;
            __threadfence();
        }
    }
}

extern "C" void kernel_launch(void* const* d_in, const int* in_sizes, int n_in,
                              void* d_out, int out_size)
{
    const float* features = (const float*)d_in[0];
    const float* masks    = (const float*)d_in[1];
    const float* conv_w   = (const float*)d_in[2];
    const float* conv_b   = (const float*)d_in[3];
    const float* bn_gamma = (const float*)d_in[4];
    const float* bn_beta  = (const float*)d_in[5];
    const float* bn_mean  = (const float*)d_in[6];
    const float* bn_var   = (const float*)d_in[7];
    const float* w1       = (const float*)d_in[8];
    const float* b1       = (const float*)d_in[9];
    const float* w2       = (const float*)d_in[10];
    const float* b2       = (const float*)d_in[11];
    float* out = (float*)d_out;

    kernelA<<<642, 128>>>(features, masks, conv_w, conv_b,
                          bn_gamma, bn_beta, bn_mean, bn_var,
                          w1, w2, b1, b2, out);
}

// round 11
// speedup vs baseline: 1.4682x; 1.4682x over previous
#include <cuda_runtime.h>

// Problem constants (fixed by the dataset)
#define BB   16
#define NN   32
#define HH   512
#define WW   512
#define CC   512
#define SS   256    // 16*16 pooled spatial
#define EE   128

// Scratch (static device globals — zero-initialized at load; the kernel
// restores the zeroed state before exit so graph replays stay deterministic).
__device__ float g_obj[BB * NN * EE];    // 256 KB: pooled numerators (REDG accum)
__device__ float g_mr[BB * NN * SS];     // resized masks [bn][s]
__device__ float g_minv[BB * NN];        // 1/(mask_sum + eps)
__device__ float g_w1T[EE * EE];         // w1 transposed [k][e]
__device__ float g_w2T[EE * EE];         // w2 transposed [k][e]
__device__ int   g_ctr;                  // mask+transpose blocks done (target 514)
__device__ int   g_done;                 // GEMM blocks done with obj atomics (128)
__device__ int   g_fin;                  // GEMM blocks fully done (last resets all)

// Swizzled index into the 64x64 proj staging tile (quad rotation).
__device__ __forceinline__ int sp_idx(int ls, int e) {
    return ls * 64 + ((((e >> 2) + (ls >> 2)) & 15) << 2) + (e & 3);
}

#define SW(bf,k,e) sBuf[(bf)*1088 + (k)*68 + (e)]
#define SF(bf,k,s) sBuf[2176 + (bf)*1088 + (k)*68 + (s)]

// ---------------------------------------------------------------------------
// Single fused kernel (128 threads/block, grid 642):
//   blocks [0,128):   GEMM 64Ex64SxK512 (scalar FFMA) + BN/ReLU + pooling
//                     GEMM2 -> REDG g_obj -> device barrier -> 4-row MLP.
//   blocks [128,640): bilinear mask resize + sums -> g_ctr.
//   blocks 640,641:   transpose w1/w2 -> g_w1T/g_w2T -> g_ctr.
// ---------------------------------------------------------------------------
__global__ void __launch_bounds__(128) kernelA(
    const float* __restrict__ features,   // [B, C, 16, 16]
    const float* __restrict__ masks,      // [B, N, 512, 512]
    const float* __restrict__ conv_w,     // [E, C]
    const float* __restrict__ conv_b,
    const float* __restrict__ bn_gamma, const float* __restrict__ bn_beta,
    const float* __restrict__ bn_mean,  const float* __restrict__ bn_var,
    const float* __restrict__ w1, const float* __restrict__ w2,
    const float* __restrict__ b1, const float* __restrict__ b2,
    float* __restrict__ out)
{
    __shared__ float sBuf[4352];          // sW/sF buffers -> sP tile -> MLP xs/hs
    __shared__ float smr[NN][64];         // mask tile [n][local s]
    __shared__ float red[4];

    const int blk = blockIdx.x;
    const int tid = threadIdx.x;

    if (blk >= 640) {
        // ---------------- weight transpose path (aliases sBuf) -------------
        float (*ttile)[33] = (float (*)[33])sBuf;
        const float* src = (blk == 640) ? w1 : w2;
        float* dstT      = (blk == 640) ? g_w1T : g_w2T;
        const int rr = tid >> 5;
        const int cc = tid & 31;
        for (int t = 0; t < 16; t++) {
            const int ti = t >> 2, tj = t & 3;
            #pragma unroll
            for (int rs = 0; rs < 8; rs++) {
                const int row = rs * 4 + rr;
                ttile[row][cc] = src[(size_t)(ti * 32 + row) * EE + tj * 32 + cc];
            }
            __syncthreads();
            #pragma unroll
            for (int rs = 0; rs < 8; rs++) {
                const int row = rs * 4 + rr;
                dstT[(size_t)(tj * 32 + row) * EE + ti * 32 + cc] = ttile[cc][row];
            }
            __syncthreads();
        }
        __threadfence();
        if (tid == 0) atomicAdd(&g_ctr, 1);
        return;
    }

    if (blk >= 128) {
        // ---------------- mask resize path ----------------
        const int bn = blk - 128;                 // 0..511
        const float* m = masks + (size_t)bn * (HH * WW);
        float lsum = 0.0f;

        #pragma unroll
        for (int rep = 0; rep < 2; rep++) {
            const int t = tid + rep * 128;        // pooled pixel 0..255
            const int o = t >> 4;
            const int p = t & 15;
            float sy = (o + 0.5f) * ((float)HH / 16.0f) - 0.5f;
            sy = fmaxf(sy, 0.0f);
            int   y0 = (int)floorf(sy);
            float fy = sy - (float)y0;
            int   y1 = min(y0 + 1, HH - 1);
            float sx = (p + 0.5f) * ((float)WW / 16.0f) - 0.5f;
            sx = fmaxf(sx, 0.0f);
            int   x0 = (int)floorf(sx);
            float fx = sx - (float)x0;
            int   x1 = min(x0 + 1, WW - 1);

            float v00 = m[(size_t)y0 * WW + x0];
            float v01 = m[(size_t)y0 * WW + x1];
            float v10 = m[(size_t)y1 * WW + x0];
            float v11 = m[(size_t)y1 * WW + x1];
            float v = (1.0f - fy) * ((1.0f - fx) * v00 + fx * v01)
                    +          fy * ((1.0f - fx) * v10 + fx * v11);

            g_mr[(size_t)bn * SS + t] = v;
            lsum += v;
        }
        __threadfence();   // publish g_mr stores before the flag
        #pragma unroll
        for (int off = 16; off > 0; off >>= 1)
            lsum += __shfl_xor_sync(0xFFFFFFFFu, lsum, off);
        if ((tid & 31) == 0) red[tid >> 5] = lsum;
        __syncthreads();
        if (tid == 0) {
            g_minv[bn] = 1.0f / (red[0] + red[1] + red[2] + red[3] + 1e-8f);
            __threadfence();
            atomicAdd(&g_ctr, 1);
        }
        return;
    }

    // ---------------- GEMM path ----------------
    const int et    = blk >> 6;           // 0..1  (E tile of 64)
    const int stile = blk & 63;           // 0..63
    const int b     = stile >> 2;
    const int s0    = (stile & 3) * 64;
    const int eBase = et * 64;

    const int te = tid >> 4;              // 0..7  -> e micro-row = te*8
    const int ts = tid & 15;              // 0..15 -> s micro-col = ts*4

    // W load: coalesced row segments, transposed on smem store
    const int wq  = tid & 3;
    const int wei = tid >> 2;             // 0..31 (rows wei, wei+32)
    const float* wp = conv_w + (size_t)(eBase + wei) * CC + (wq << 2);

    // F load: [k][s] coalesced
    const int fk  = tid >> 4;             // 0..7
    const int fsq = (tid & 15) << 2;
    const float* fp = features + ((size_t)b * CC + fk) * SS + s0 + fsq;

    float acc[8][4];
    #pragma unroll
    for (int i = 0; i < 8; i++)
        #pragma unroll
        for (int j = 0; j < 4; j++) acc[i][j] = 0.0f;

    float4 wr0 = *(const float4*)wp;
    float4 wr1 = *(const float4*)(wp + 32 * CC);
    float4 fr0 = *(const float4*)fp;
    float4 fr1 = *(const float4*)(fp + 8 * SS);

    {
        const int kk = wq << 2;
        SW(0, kk + 0, wei) = wr0.x;  SW(0, kk + 0, wei + 32) = wr1.x;
        SW(0, kk + 1, wei) = wr0.y;  SW(0, kk + 1, wei + 32) = wr1.y;
        SW(0, kk + 2, wei) = wr0.z;  SW(0, kk + 2, wei + 32) = wr1.z;
        SW(0, kk + 3, wei) = wr0.w;  SW(0, kk + 3, wei + 32) = wr1.w;
        *(float4*)&SF(0, fk, fsq)     = fr0;
        *(float4*)&SF(0, fk + 8, fsq) = fr1;
    }
    __syncthreads();

    #pragma unroll 1
    for (int t = 0; t < 32; t++) {
        const int cur = t & 1;
        if (t < 31) {
            const int c0 = (t + 1) << 4;
            wr0 = *(const float4*)(wp + c0);
            wr1 = *(const float4*)(wp + 32 * CC + c0);
            fr0 = *(const float4*)(fp + (size_t)c0 * SS);
            fr1 = *(const float4*)(fp + (size_t)(c0 + 8) * SS);
        }
        #pragma unroll
        for (int k = 0; k < 16; k++) {
            float4 a0 = *(const float4*)&SW(cur, k, te << 3);
            float4 a1 = *(const float4*)&SW(cur, k, (te << 3) + 4);
            float4 f  = *(const float4*)&SF(cur, k, ts << 2);
            float av[8] = {a0.x, a0.y, a0.z, a0.w, a1.x, a1.y, a1.z, a1.w};
            float fv[4] = {f.x, f.y, f.z, f.w};
            #pragma unroll
            for (int i = 0; i < 8; i++)
                #pragma unroll
                for (int j = 0; j < 4; j++)
                    acc[i][j] += av[i] * fv[j];
        }
        if (t < 31) {
            const int nxt = cur ^ 1;
            const int kk = wq << 2;
            SW(nxt, kk + 0, wei) = wr0.x;  SW(nxt, kk + 0, wei + 32) = wr1.x;
            SW(nxt, kk + 1, wei) = wr0.y;  SW(nxt, kk + 1, wei + 32) = wr1.y;
            SW(nxt, kk + 2, wei) = wr0.z;  SW(nxt, kk + 2, wei + 32) = wr1.z;
            SW(nxt, kk + 3, wei) = wr0.w;  SW(nxt, kk + 3, wei + 32) = wr1.w;
            *(float4*)&SF(nxt, fk, fsq)     = fr0;
            *(float4*)&SF(nxt, fk + 8, fsq) = fr1;
        }
        __syncthreads();
    }

    // BN + ReLU in registers, then stage the proj tile into sBuf (swizzled).
    {
        float scv[8], bv[8];
        #pragma unroll
        for (int i = 0; i < 8; i++) {
            const int e = eBase + (te << 3) + i;
            scv[i] = bn_gamma[e] * rsqrtf(bn_var[e] + 1e-5f);
            bv[i]  = (conv_b[e] - bn_mean[e]) * scv[i] + bn_beta[e];
        }
        #pragma unroll
        for (int j = 0; j < 4; j++) {
            const int ls = (ts << 2) + j;
            float4 o0, o1;
            o0.x = fmaxf(acc[0][j] * scv[0] + bv[0], 0.f);
            o0.y = fmaxf(acc[1][j] * scv[1] + bv[1], 0.f);
            o0.z = fmaxf(acc[2][j] * scv[2] + bv[2], 0.f);
            o0.w = fmaxf(acc[3][j] * scv[3] + bv[3], 0.f);
            o1.x = fmaxf(acc[4][j] * scv[4] + bv[4], 0.f);
            o1.y = fmaxf(acc[5][j] * scv[5] + bv[5], 0.f);
            o1.z = fmaxf(acc[6][j] * scv[6] + bv[6], 0.f);
            o1.w = fmaxf(acc[7][j] * scv[7] + bv[7], 0.f);
            *(float4*)&sBuf[sp_idx(ls, (te << 3))]     = o0;
            *(float4*)&sBuf[sp_idx(ls, (te << 3) + 4)] = o1;
        }
    }

    // Wait for all mask + transpose blocks (they finish long before the K-loop).
    if (tid == 0) {
        while (*(volatile int*)&g_ctr < 514) __nanosleep(100);
    }
    __syncthreads();
    __threadfence();

    // Load this block's mask tile [32 n][64 s]
    for (int i = tid; i < NN * 64; i += 128)
        smr[i >> 6][i & 63] = g_mr[(size_t)(b * NN + (i >> 6)) * SS + s0 + (i & 63)];
    __syncthreads();

    // GEMM2: obj_partial[n][e] = sum_ls smr[n][ls] * proj[ls][e]
    {
        const int tn = tid >> 4;          // 0..7 -> n0 = 4*tn
        const int tc = tid & 15;          // e0 = 4*tc
        float ob[4][4];
        #pragma unroll
        for (int r = 0; r < 4; r++)
            #pragma unroll
            for (int c = 0; c < 4; c++) ob[r][c] = 0.f;

        #pragma unroll 4
        for (int ls = 0; ls < 64; ls++) {
            float4 pv = *(const float4*)&sBuf[sp_idx(ls, tc << 2)];
            #pragma unroll
            for (int r = 0; r < 4; r++) {
                const float m = smr[(tn << 2) + r][ls];
                ob[r][0] += m * pv.x;
                ob[r][1] += m * pv.y;
                ob[r][2] += m * pv.z;
                ob[r][3] += m * pv.w;
            }
        }
        #pragma unroll
        for (int r = 0; r < 4; r++) {
            float* dst = &g_obj[(size_t)(b * NN + (tn << 2) + r) * EE
                                + eBase + (tc << 2)];
            #pragma unroll
            for (int c = 0; c < 4; c++)
                atomicAdd(dst + c, ob[r][c]);
        }
    }

    // -------- device barrier: all GEMM blocks' obj atomics visible ---------
    __threadfence();
    __syncthreads();
    if (tid == 0) {
        atomicAdd(&g_done, 1);
        while (*(volatile int*)&g_done < 128) __nanosleep(100);
    }
    __syncthreads();
    __threadfence();

    // -------- MLP for this block's 4 (b,n) rows: rows bn0..bn0+3 ----------
    {
        float* xs = sBuf;                 // [4][132]
        float* hs = sBuf + 4 * 132;       // [4][132]
        const int bn0 = blk << 2;
        const int e = tid;

        #pragma unroll
        for (int r = 0; r < 4; r++) {
            const size_t idx = (size_t)(bn0 + r) * EE + e;
            xs[r * 132 + e] = g_obj[idx] * g_minv[bn0 + r];
            g_obj[idx] = 0.f;             // restore zeros for next graph replay
        }
        __syncthreads();

        // layer 1
        {
            float a0 = 0.f, a1 = 0.f, a2 = 0.f, a3 = 0.f;
            const float* wt = g_w1T + e;
            #pragma unroll 8
            for (int k = 0; k < EE; k++) {
                const float wv = wt[k << 7];
                a0 += wv * xs[0 * 132 + k];
                a1 += wv * xs[1 * 132 + k];
                a2 += wv * xs[2 * 132 + k];
                a3 += wv * xs[3 * 132 + k];
            }
            const float bb = b1[e];
            hs[0 * 132 + e] = fmaxf(a0 + bb, 0.f);
            hs[1 * 132 + e] = fmaxf(a1 + bb, 0.f);
            hs[2 * 132 + e] = fmaxf(a2 + bb, 0.f);
            hs[3 * 132 + e] = fmaxf(a3 + bb, 0.f);
        }
        __syncthreads();

        // layer 2
        {
            float a0 = 0.f, a1 = 0.f, a2 = 0.f, a3 = 0.f;
            const float* wt = g_w2T + e;
            #pragma unroll 8
            for (int k = 0; k < EE; k++) {
                const float wv = wt[k << 7];
                a0 += wv * hs[0 * 132 + k];
                a1 += wv * hs[1 * 132 + k];
                a2 += wv * hs[2 * 132 + k];
                a3 += wv * hs[3 * 132 + k];
            }
            const float bb = b2[e];
            out[(size_t)(bn0 + 0) * EE + e] = a0 + bb;
            out[(size_t)(bn0 + 1) * EE + e] = a1 + bb;
            out[(size_t)(bn0 + 2) * EE + e] = a2 + bb;
            out[(size_t)(bn0 + 3) * EE + e] = a3 + bb;
        }
    }

    // -------- last-one-out: reset counters for the next graph replay -------
    __syncthreads();
    if (tid == 0) {
        __threadfence();
        const int prev = atomicAdd(&g_fin, 1);
        if (prev == 127) {                // last GEMM block out
            g_ctr = 0;
            g_done = 0;
            g_fin = 0;
            __threadfence();
        }
    }
}

extern "C" void kernel_launch(void* const* d_in, const int* in_sizes, int n_in,
                              void* d_out, int out_size)
{
    const float* features = (const float*)d_in[0];
    const float* masks    = (const float*)d_in[1];
    const float* conv_w   = (const float*)d_in[2];
    const float* conv_b   = (const float*)d_in[3];
    const float* bn_gamma = (const float*)d_in[4];
    const float* bn_beta  = (const float*)d_in[5];
    const float* bn_mean  = (const float*)d_in[6];
    const float* bn_var   = (const float*)d_in[7];
    const float* w1       = (const float*)d_in[8];
    const float* b1       = (const float*)d_in[9];
    const float* w2       = (const float*)d_in[10];
    const float* b2       = (const float*)d_in[11];
    float* out = (float*)d_out;

    kernelA<<<642, 128>>>(features, masks, conv_w, conv_b,
                          bn_gamma, bn_beta, bn_mean, bn_var,
                          w1, w2, b1, b2, out);
}

// round 12
// speedup vs baseline: 1.4817x; 1.0092x over previous
#include <cuda_runtime.h>

// Problem constants (fixed by the dataset)
#define BB   16
#define NN   32
#define HH   512
#define WW   512
#define CC   512
#define SS   256    // 16*16 pooled spatial
#define EE   128

// Scratch (static device globals — zero-initialized at load; kernelB restores
// the zeroed state after each use so graph replays stay deterministic).
__device__ float g_obj[BB * NN * EE];    // 256 KB: pooled numerators (REDG accum)
__device__ float g_mr[BB * NN * SS];     // resized masks [bn][s]
__device__ float g_minv[BB * NN];        // 1/(mask_sum + eps)
__device__ float g_w1T[EE * EE];         // w1 transposed [k][e]
__device__ float g_w2T[EE * EE];         // w2 transposed [k][e]
__device__ int   g_ctr;                  // mask blocks done (target 512)

// Swizzled index into the 64x64 proj staging tile (quad rotation).
__device__ __forceinline__ int sp_idx(int ls, int e) {
    return ls * 64 + ((((e >> 2) + (ls >> 2)) & 15) << 2) + (e & 3);
}

#define SW(bf,k,e) sBuf[(bf)*1088 + (k)*68 + (e)]
#define SF(bf,k,s) sBuf[2176 + (bf)*1088 + (k)*68 + (s)]

// ---------------------------------------------------------------------------
// Kernel A (256 threads/block, grid 642):
//   blocks [0,128):   GEMM 64Ex64SxK512, microtile 4x4 (2 warps/SMSP for
//                     latency hiding) + BN/ReLU + pooling GEMM2 -> REDG g_obj.
//   blocks [128,640): bilinear mask resize + sums -> g_ctr.
//   blocks 640,641:   transpose w1/w2 -> g_w1T/g_w2T.
// ---------------------------------------------------------------------------
__global__ void __launch_bounds__(256) kernelA(
    const float* __restrict__ features,   // [B, C, 16, 16]
    const float* __restrict__ masks,      // [B, N, 512, 512]
    const float* __restrict__ conv_w,     // [E, C]
    const float* __restrict__ conv_b,
    const float* __restrict__ bn_gamma, const float* __restrict__ bn_beta,
    const float* __restrict__ bn_mean,  const float* __restrict__ bn_var,
    const float* __restrict__ w1, const float* __restrict__ w2)
{
    __shared__ float sBuf[4352];          // sW/sF double buffers -> sP tile
    __shared__ float smr[NN][64];         // mask tile [n][local s]
    __shared__ float red[8];

    const int blk = blockIdx.x;
    const int tid = threadIdx.x;

    if (blk >= 640) {
        // ---------------- weight transpose path (aliases sBuf) -------------
        float (*ttile)[33] = (float (*)[33])sBuf;
        const float* src = (blk == 640) ? w1 : w2;
        float* dstT      = (blk == 640) ? g_w1T : g_w2T;
        const int rr = tid >> 5;            // 0..7
        const int cc = tid & 31;
        for (int t = 0; t < 16; t++) {
            const int ti = t >> 2, tj = t & 3;
            #pragma unroll
            for (int q = 0; q < 4; q++) {
                const int row = q * 8 + rr;
                ttile[row][cc] = src[(size_t)(ti * 32 + row) * EE + tj * 32 + cc];
            }
            __syncthreads();
            #pragma unroll
            for (int q = 0; q < 4; q++) {
                const int row = q * 8 + rr;
                dstT[(size_t)(tj * 32 + row) * EE + ti * 32 + cc] = ttile[cc][row];
            }
            __syncthreads();
        }
        return;
    }

    if (blk >= 128) {
        // ---------------- mask resize path (one pixel per thread) ----------
        const int bn = blk - 128;                 // 0..511
        const float* m = masks + (size_t)bn * (HH * WW);

        const int o = tid >> 4;                   // out row 0..15
        const int p = tid & 15;                   // out col 0..15
        float sy = (o + 0.5f) * ((float)HH / 16.0f) - 0.5f;
        sy = fmaxf(sy, 0.0f);
        int   y0 = (int)floorf(sy);
        float fy = sy - (float)y0;
        int   y1 = min(y0 + 1, HH - 1);
        float sx = (p + 0.5f) * ((float)WW / 16.0f) - 0.5f;
        sx = fmaxf(sx, 0.0f);
        int   x0 = (int)floorf(sx);
        float fx = sx - (float)x0;
        int   x1 = min(x0 + 1, WW - 1);

        float v00 = m[(size_t)y0 * WW + x0];
        float v01 = m[(size_t)y0 * WW + x1];
        float v10 = m[(size_t)y1 * WW + x0];
        float v11 = m[(size_t)y1 * WW + x1];
        float v = (1.0f - fy) * ((1.0f - fx) * v00 + fx * v01)
                +          fy * ((1.0f - fx) * v10 + fx * v11);

        g_mr[(size_t)bn * SS + tid] = v;
        __threadfence();                   // publish g_mr before the flag

        float lsum = v;
        #pragma unroll
        for (int off = 16; off > 0; off >>= 1)
            lsum += __shfl_xor_sync(0xFFFFFFFFu, lsum, off);
        if ((tid & 31) == 0) red[tid >> 5] = lsum;
        __syncthreads();
        if (tid == 0) {
            float s = red[0] + red[1] + red[2] + red[3]
                    + red[4] + red[5] + red[6] + red[7];
            g_minv[bn] = 1.0f / (s + 1e-8f);
            __threadfence();
            atomicAdd(&g_ctr, 1);
        }
        return;
    }

    // ---------------- GEMM path ----------------
    const int et    = blk >> 6;           // 0..1  (E tile of 64)
    const int stile = blk & 63;           // 0..63
    const int b     = stile >> 2;
    const int s0    = (stile & 3) * 64;
    const int eBase = et * 64;

    // microtile 4E x 4S: threads as 16 x 16
    const int te = tid >> 4;              // 0..15 -> e = te*4
    const int ts = tid & 15;              // 0..15 -> s = ts*4

    // global load roles: warps 0-3 load W, warps 4-7 load F
    const int isW = (tid < 128);
    const int wq  = tid & 3;              // W c-quad
    const int wei = (tid >> 2) & 31;      // W rows wei, wei+32
    const int t2  = tid & 127;
    const int fk  = t2 >> 4;              // 0..7 -> F k rows fk, fk+8
    const int fsq = (t2 & 15) << 2;       // F s col (x4)

    const float* wp = conv_w + (size_t)(eBase + wei) * CC + (wq << 2);
    const float* fp = features + ((size_t)b * CC + fk) * SS + s0 + fsq;

    float acc[4][4];
    #pragma unroll
    for (int i = 0; i < 4; i++)
        #pragma unroll
        for (int j = 0; j < 4; j++) acc[i][j] = 0.0f;

    float4 r0, r1;
    if (isW) {
        r0 = *(const float4*)wp;
        r1 = *(const float4*)(wp + 32 * CC);
    } else {
        r0 = *(const float4*)fp;
        r1 = *(const float4*)(fp + 8 * SS);
    }

    if (isW) {
        const int kk = wq << 2;
        SW(0, kk + 0, wei) = r0.x;  SW(0, kk + 0, wei + 32) = r1.x;
        SW(0, kk + 1, wei) = r0.y;  SW(0, kk + 1, wei + 32) = r1.y;
        SW(0, kk + 2, wei) = r0.z;  SW(0, kk + 2, wei + 32) = r1.z;
        SW(0, kk + 3, wei) = r0.w;  SW(0, kk + 3, wei + 32) = r1.w;
    } else {
        *(float4*)&SF(0, fk, fsq)     = r0;
        *(float4*)&SF(0, fk + 8, fsq) = r1;
    }
    __syncthreads();

    #pragma unroll 1
    for (int t = 0; t < 32; t++) {
        const int cur = t & 1;
        if (t < 31) {                       // prefetch next k-tile
            const int c0 = (t + 1) << 4;
            if (isW) {
                r0 = *(const float4*)(wp + c0);
                r1 = *(const float4*)(wp + 32 * CC + c0);
            } else {
                r0 = *(const float4*)(fp + (size_t)c0 * SS);
                r1 = *(const float4*)(fp + (size_t)(c0 + 8) * SS);
            }
        }
        #pragma unroll
        for (int k = 0; k < 16; k++) {
            float4 a = *(const float4*)&SW(cur, k, te << 2);
            float4 f = *(const float4*)&SF(cur, k, ts << 2);
            float av[4] = {a.x, a.y, a.z, a.w};
            float fv[4] = {f.x, f.y, f.z, f.w};
            #pragma unroll
            for (int i = 0; i < 4; i++)
                #pragma unroll
                for (int j = 0; j < 4; j++)
                    acc[i][j] += av[i] * fv[j];
        }
        if (t < 31) {                       // fill the other buffer
            const int nxt = cur ^ 1;
            if (isW) {
                const int kk = wq << 2;
                SW(nxt, kk + 0, wei) = r0.x;  SW(nxt, kk + 0, wei + 32) = r1.x;
                SW(nxt, kk + 1, wei) = r0.y;  SW(nxt, kk + 1, wei + 32) = r1.y;
                SW(nxt, kk + 2, wei) = r0.z;  SW(nxt, kk + 2, wei + 32) = r1.z;
                SW(nxt, kk + 3, wei) = r0.w;  SW(nxt, kk + 3, wei + 32) = r1.w;
            } else {
                *(float4*)&SF(nxt, fk, fsq)     = r0;
                *(float4*)&SF(nxt, fk + 8, fsq) = r1;
            }
        }
        __syncthreads();
    }

    // BN + ReLU in registers, then stage the proj tile into sBuf (swizzled).
    {
        float scv[4], bv[4];
        #pragma unroll
        for (int i = 0; i < 4; i++) {
            const int e = eBase + (te << 2) + i;
            scv[i] = bn_gamma[e] * rsqrtf(bn_var[e] + 1e-5f);
            bv[i]  = (conv_b[e] - bn_mean[e]) * scv[i] + bn_beta[e];
        }
        #pragma unroll
        for (int j = 0; j < 4; j++) {
            const int ls = (ts << 2) + j;
            float4 o;
            o.x = fmaxf(acc[0][j] * scv[0] + bv[0], 0.f);
            o.y = fmaxf(acc[1][j] * scv[1] + bv[1], 0.f);
            o.z = fmaxf(acc[2][j] * scv[2] + bv[2], 0.f);
            o.w = fmaxf(acc[3][j] * scv[3] + bv[3], 0.f);
            *(float4*)&sBuf[sp_idx(ls, te << 2)] = o;
        }
    }

    // Wait for all mask blocks (they finish long before the K-loop does).
    if (tid == 0) {
        while (*(volatile int*)&g_ctr < 512) __nanosleep(100);
    }
    __syncthreads();
    __threadfence();

    // Load this block's mask tile [32 n][64 s]
    for (int i = tid; i < NN * 64; i += 256)
        smr[i >> 6][i & 63] = g_mr[(size_t)(b * NN + (i >> 6)) * SS + s0 + (i & 63)];
    __syncthreads();

    // GEMM2: obj_partial[n][e] = sum_ls smr[n][ls] * proj[ls][e]
    // 256 threads: tn = tid>>4 (2 n-rows each), tc = tid&15 (4 e each)
    {
        const int tn = tid >> 4;          // 0..15 -> n rows 2tn, 2tn+1
        const int tc = tid & 15;          // e0 = 4*tc
        float ob[2][4];
        #pragma unroll
        for (int r = 0; r < 2; r++)
            #pragma unroll
            for (int c = 0; c < 4; c++) ob[r][c] = 0.f;

        #pragma unroll 4
        for (int ls = 0; ls < 64; ls++) {
            float4 pv = *(const float4*)&sBuf[sp_idx(ls, tc << 2)];
            #pragma unroll
            for (int r = 0; r < 2; r++) {
                const float m = smr[(tn << 1) + r][ls];
                ob[r][0] += m * pv.x;
                ob[r][1] += m * pv.y;
                ob[r][2] += m * pv.z;
                ob[r][3] += m * pv.w;
            }
        }
        #pragma unroll
        for (int r = 0; r < 2; r++) {
            float* dst = &g_obj[(size_t)(b * NN + (tn << 1) + r) * EE
                                + eBase + (tc << 2)];
            #pragma unroll
            for (int c = 0; c < 4; c++)
                atomicAdd(dst + c, ob[r][c]);
        }
    }
}

// ---------------------------------------------------------------------------
// Kernel B: obj normalize + 2-layer MLP. Grid 128 = (b, ngroup of 4),
// 512 threads: tid = part*128 + e; part splits the 128-k reduction 4 ways.
// Also restores zeroed scratch state for graph replay.
// ---------------------------------------------------------------------------
__global__ void __launch_bounds__(512) kernelB(
    const float* __restrict__ b1, const float* __restrict__ b2,
    float* __restrict__ out)
{
    const int b  = blockIdx.x >> 3;
    const int ng = blockIdx.x & 7;
    const int n0 = ng * 4;
    const int tid  = threadIdx.x;
    const int e    = tid & 127;
    const int part = tid >> 7;           // 0..3

    __shared__ float px[4][4][EE];       // partials [part][row][e]
    __shared__ float xs[4][EE];
    __shared__ float hs[4][EE];
    __shared__ float inv[4];

    if (tid < 4) inv[tid] = g_minv[b * NN + n0 + tid];
    __syncthreads();
    {
        const size_t idx = (size_t)(b * NN + n0 + part) * EE + e;
        xs[part][e] = g_obj[idx] * inv[part];
        g_obj[idx] = 0.f;                 // restore for next graph replay
    }
    if (blockIdx.x == 0 && tid == 0) g_ctr = 0;
    __syncthreads();

    // layer 1 partials over k-quarter (coalesced w1T reads)
    {
        float h0 = 0.f, h1 = 0.f, h2 = 0.f, h3 = 0.f;
        const float* wt = g_w1T + (size_t)(part * 32) * EE + e;
        #pragma unroll 8
        for (int kk = 0; kk < 32; kk++) {
            const float wv = wt[(size_t)kk * EE];
            const int k = part * 32 + kk;
            h0 += wv * xs[0][k];
            h1 += wv * xs[1][k];
            h2 += wv * xs[2][k];
            h3 += wv * xs[3][k];
        }
        px[part][0][e] = h0;
        px[part][1][e] = h1;
        px[part][2][e] = h2;
        px[part][3][e] = h3;
    }
    __syncthreads();

    hs[part][e] = fmaxf(px[0][part][e] + px[1][part][e] + px[2][part][e]
                        + px[3][part][e] + b1[e], 0.f);
    __syncthreads();

    // layer 2 partials
    {
        float h0 = 0.f, h1 = 0.f, h2 = 0.f, h3 = 0.f;
        const float* wt = g_w2T + (size_t)(part * 32) * EE + e;
        #pragma unroll 8
        for (int kk = 0; kk < 32; kk++) {
            const float wv = wt[(size_t)kk * EE];
            const int k = part * 32 + kk;
            h0 += wv * hs[0][k];
            h1 += wv * hs[1][k];
            h2 += wv * hs[2][k];
            h3 += wv * hs[3][k];
        }
        px[part][0][e] = h0;
        px[part][1][e] = h1;
        px[part][2][e] = h2;
        px[part][3][e] = h3;
    }
    __syncthreads();

    out[((size_t)(b * NN + n0 + part)) * EE + e] =
        px[0][part][e] + px[1][part][e] + px[2][part][e] + px[3][part][e] + b2[e];
}

extern "C" void kernel_launch(void* const* d_in, const int* in_sizes, int n_in,
                              void* d_out, int out_size)
{
    const float* features = (const float*)d_in[0];
    const float* masks    = (const float*)d_in[1];
    const float* conv_w   = (const float*)d_in[2];
    const float* conv_b   = (const float*)d_in[3];
    const float* bn_gamma = (const float*)d_in[4];
    const float* bn_beta  = (const float*)d_in[5];
    const float* bn_mean  = (const float*)d_in[6];
    const float* bn_var   = (const float*)d_in[7];
    const float* w1       = (const float*)d_in[8];
    const float* b1       = (const float*)d_in[9];
    const float* w2       = (const float*)d_in[10];
    const float* b2       = (const float*)d_in[11];
    float* out = (float*)d_out;

    kernelA<<<642, 256>>>(features, masks, conv_w, conv_b,
                          bn_gamma, bn_beta, bn_mean, bn_var, w1, w2);
    kernelB<<<128, 512>>>(b1, b2, out);
}

// round 13
// speedup vs baseline: 1.7907x; 1.2086x over previous
#include <cuda_runtime.h>

// Problem constants (fixed by the dataset)
#define BB   16
#define NN   32
#define HH   512
#define WW   512
#define CC   512
#define SS   256    // 16*16 pooled spatial
#define EE   128

// Scratch (static device globals — zero-initialized at load; kernelB restores
// the zeroed state after each use so graph replays stay deterministic).
__device__ float g_obj[BB * NN * EE];    // 256 KB: pooled numerators (REDG accum)
__device__ float g_mr[BB * NN * SS];     // resized masks [bn][s]
__device__ float g_minv[BB * NN];        // 1/(mask_sum + eps)
__device__ float g_w1T[EE * EE];         // w1 transposed [k][e]
__device__ float g_w2T[EE * EE];         // w2 transposed [k][e]
__device__ int   g_ctr;                  // mask blocks done (target 512)

// Swizzled index into the 64x64 proj staging tile (quad rotation).
__device__ __forceinline__ int sp_idx(int ls, int e) {
    return ls * 64 + ((((e >> 2) + (ls >> 2)) & 15) << 2) + (e & 3);
}

// Per-warpgroup double-buffered K-tile storage (two independent halves).
#define SWX(g,bf,k,e) sBuf[(g)*4352 + (bf)*1088 + (k)*68 + (e)]
#define SFX(g,bf,k,s) sBuf[(g)*4352 + 2176 + (bf)*1088 + (k)*68 + (s)]

// ---------------------------------------------------------------------------
// Kernel A (256 threads/block, grid 642):
//   blocks [0,128):   GEMM 64Ex64S, in-block split-K: warpgroup g does
//                     K in [256g, 256g+256) with the proven 8Ex4S microtile.
//                     Partial sums combined in smem, then BN/ReLU + pooling
//                     GEMM2 -> REDG into g_obj.
//   blocks [128,640): bilinear mask resize + sums -> g_ctr.
//   blocks 640,641:   transpose w1/w2 -> g_w1T/g_w2T.
// ---------------------------------------------------------------------------
__global__ void __launch_bounds__(256) kernelA(
    const float* __restrict__ features,   // [B, C, 16, 16]
    const float* __restrict__ masks,      // [B, N, 512, 512]
    const float* __restrict__ conv_w,     // [E, C]
    const float* __restrict__ conv_b,
    const float* __restrict__ bn_gamma, const float* __restrict__ bn_beta,
    const float* __restrict__ bn_mean,  const float* __restrict__ bn_var,
    const float* __restrict__ w1, const float* __restrict__ w2)
{
    __shared__ float sBuf[8704];          // 2 wg halves; later sP tile + stage
    __shared__ float smr[NN][64];         // mask tile [n][local s]
    __shared__ float red[8];

    const int blk = blockIdx.x;
    const int tid = threadIdx.x;

    if (blk >= 640) {
        // ---------------- weight transpose path (aliases sBuf) -------------
        float (*ttile)[33] = (float (*)[33])sBuf;
        const float* src = (blk == 640) ? w1 : w2;
        float* dstT      = (blk == 640) ? g_w1T : g_w2T;
        const int rr = tid >> 5;            // 0..7
        const int cc = tid & 31;
        for (int t = 0; t < 16; t++) {
            const int ti = t >> 2, tj = t & 3;
            #pragma unroll
            for (int q = 0; q < 4; q++) {
                const int row = q * 8 + rr;
                ttile[row][cc] = src[(size_t)(ti * 32 + row) * EE + tj * 32 + cc];
            }
            __syncthreads();
            #pragma unroll
            for (int q = 0; q < 4; q++) {
                const int row = q * 8 + rr;
                dstT[(size_t)(tj * 32 + row) * EE + ti * 32 + cc] = ttile[cc][row];
            }
            __syncthreads();
        }
        return;
    }

    if (blk >= 128) {
        // ---------------- mask resize path (one pixel per thread) ----------
        const int bn = blk - 128;                 // 0..511
        const float* m = masks + (size_t)bn * (HH * WW);

        const int o = tid >> 4;                   // out row 0..15
        const int p = tid & 15;                   // out col 0..15
        float sy = (o + 0.5f) * ((float)HH / 16.0f) - 0.5f;
        sy = fmaxf(sy, 0.0f);
        int   y0 = (int)floorf(sy);
        float fy = sy - (float)y0;
        int   y1 = min(y0 + 1, HH - 1);
        float sx = (p + 0.5f) * ((float)WW / 16.0f) - 0.5f;
        sx = fmaxf(sx, 0.0f);
        int   x0 = (int)floorf(sx);
        float fx = sx - (float)x0;
        int   x1 = min(x0 + 1, WW - 1);

        float v00 = m[(size_t)y0 * WW + x0];
        float v01 = m[(size_t)y0 * WW + x1];
        float v10 = m[(size_t)y1 * WW + x0];
        float v11 = m[(size_t)y1 * WW + x1];
        float v = (1.0f - fy) * ((1.0f - fx) * v00 + fx * v01)
                +          fy * ((1.0f - fx) * v10 + fx * v11);

        g_mr[(size_t)bn * SS + tid] = v;
        __threadfence();                   // publish g_mr before the flag

        float lsum = v;
        #pragma unroll
        for (int off = 16; off > 0; off >>= 1)
            lsum += __shfl_xor_sync(0xFFFFFFFFu, lsum, off);
        if ((tid & 31) == 0) red[tid >> 5] = lsum;
        __syncthreads();
        if (tid == 0) {
            float s = red[0] + red[1] + red[2] + red[3]
                    + red[4] + red[5] + red[6] + red[7];
            g_minv[bn] = 1.0f / (s + 1e-8f);
            __threadfence();
            atomicAdd(&g_ctr, 1);
        }
        return;
    }

    // ---------------- GEMM path (in-block split-K) ----------------
    const int et    = blk >> 6;           // 0..1  (E tile of 64)
    const int stile = blk & 63;           // 0..63
    const int b     = stile >> 2;
    const int s0    = (stile & 3) * 64;
    const int eBase = et * 64;

    const int wg = tid >> 7;              // warpgroup: K-half
    const int lt = tid & 127;
    const int kb = wg << 8;               // K base: 0 or 256

    const int te = lt >> 4;               // 0..7  -> e micro-row = te*8
    const int ts = lt & 15;               // 0..15 -> s micro-col = ts*4

    // W load: coalesced row segments, transposed on smem store
    const int wq  = lt & 3;
    const int wei = lt >> 2;              // 0..31 (rows wei, wei+32)
    const float* wp = conv_w + (size_t)(eBase + wei) * CC + kb + (wq << 2);

    // F load: [k][s] coalesced
    const int fk  = lt >> 4;              // 0..7
    const int fsq = (lt & 15) << 2;
    const float* fp = features + ((size_t)b * CC + kb + fk) * SS + s0 + fsq;

    float acc[8][4];
    #pragma unroll
    for (int i = 0; i < 8; i++)
        #pragma unroll
        for (int j = 0; j < 4; j++) acc[i][j] = 0.0f;

    float4 wr0 = *(const float4*)wp;
    float4 wr1 = *(const float4*)(wp + 32 * CC);
    float4 fr0 = *(const float4*)fp;
    float4 fr1 = *(const float4*)(fp + 8 * SS);

    {
        const int kk = wq << 2;
        SWX(wg, 0, kk + 0, wei) = wr0.x;  SWX(wg, 0, kk + 0, wei + 32) = wr1.x;
        SWX(wg, 0, kk + 1, wei) = wr0.y;  SWX(wg, 0, kk + 1, wei + 32) = wr1.y;
        SWX(wg, 0, kk + 2, wei) = wr0.z;  SWX(wg, 0, kk + 2, wei + 32) = wr1.z;
        SWX(wg, 0, kk + 3, wei) = wr0.w;  SWX(wg, 0, kk + 3, wei + 32) = wr1.w;
        *(float4*)&SFX(wg, 0, fk, fsq)     = fr0;
        *(float4*)&SFX(wg, 0, fk + 8, fsq) = fr1;
    }
    __syncthreads();

    #pragma unroll 1
    for (int t = 0; t < 16; t++) {        // 16 K-tiles of 16 = 256 per wg
        const int cur = t & 1;
        if (t < 15) {
            const int c0 = (t + 1) << 4;
            wr0 = *(const float4*)(wp + c0);
            wr1 = *(const float4*)(wp + 32 * CC + c0);
            fr0 = *(const float4*)(fp + (size_t)c0 * SS);
            fr1 = *(const float4*)(fp + (size_t)(c0 + 8) * SS);
        }
        #pragma unroll
        for (int k = 0; k < 16; k++) {
            float4 a0 = *(const float4*)&SWX(wg, cur, k, te << 3);
            float4 a1 = *(const float4*)&SWX(wg, cur, k, (te << 3) + 4);
            float4 f  = *(const float4*)&SFX(wg, cur, k, ts << 2);
            float av[8] = {a0.x, a0.y, a0.z, a0.w, a1.x, a1.y, a1.z, a1.w};
            float fv[4] = {f.x, f.y, f.z, f.w};
            #pragma unroll
            for (int i = 0; i < 8; i++)
                #pragma unroll
                for (int j = 0; j < 4; j++)
                    acc[i][j] += av[i] * fv[j];
        }
        if (t < 15) {
            const int nxt = cur ^ 1;
            const int kk = wq << 2;
            SWX(wg, nxt, kk + 0, wei) = wr0.x;  SWX(wg, nxt, kk + 0, wei + 32) = wr1.x;
            SWX(wg, nxt, kk + 1, wei) = wr0.y;  SWX(wg, nxt, kk + 1, wei + 32) = wr1.y;
            SWX(wg, nxt, kk + 2, wei) = wr0.z;  SWX(wg, nxt, kk + 2, wei + 32) = wr1.z;
            SWX(wg, nxt, kk + 3, wei) = wr0.w;  SWX(wg, nxt, kk + 3, wei + 32) = wr1.w;
            *(float4*)&SFX(wg, nxt, fk, fsq)     = fr0;
            *(float4*)&SFX(wg, nxt, fk + 8, fsq) = fr1;
        }
        __syncthreads();
    }

    // Combine K-halves: wg1 spills acc to padded stage (stride 33, no bank
    // conflicts), wg0 adds. Stage reuses wg1's smem half (no longer needed).
    {
        float* stage = sBuf + 4352;       // 128*33 = 4224 <= 4352
        if (wg == 1) {
            #pragma unroll
            for (int i = 0; i < 8; i++)
                #pragma unroll
                for (int j = 0; j < 4; j++)
                    stage[lt * 33 + i * 4 + j] = acc[i][j];
        }
        __syncthreads();
        if (wg == 0) {
            #pragma unroll
            for (int i = 0; i < 8; i++)
                #pragma unroll
                for (int j = 0; j < 4; j++)
                    acc[i][j] += stage[lt * 33 + i * 4 + j];
        }
    }
    __syncthreads();                      // wg0 may now overwrite sBuf[0..4096)

    // BN + ReLU in registers (wg0 only), stage proj tile into sBuf (swizzled).
    if (wg == 0) {
        float scv[8], bv[8];
        #pragma unroll
        for (int i = 0; i < 8; i++) {
            const int e = eBase + (te << 3) + i;
            scv[i] = bn_gamma[e] * rsqrtf(bn_var[e] + 1e-5f);
            bv[i]  = (conv_b[e] - bn_mean[e]) * scv[i] + bn_beta[e];
        }
        #pragma unroll
        for (int j = 0; j < 4; j++) {
            const int ls = (ts << 2) + j;
            float4 o0, o1;
            o0.x = fmaxf(acc[0][j] * scv[0] + bv[0], 0.f);
            o0.y = fmaxf(acc[1][j] * scv[1] + bv[1], 0.f);
            o0.z = fmaxf(acc[2][j] * scv[2] + bv[2], 0.f);
            o0.w = fmaxf(acc[3][j] * scv[3] + bv[3], 0.f);
            o1.x = fmaxf(acc[4][j] * scv[4] + bv[4], 0.f);
            o1.y = fmaxf(acc[5][j] * scv[5] + bv[5], 0.f);
            o1.z = fmaxf(acc[6][j] * scv[6] + bv[6], 0.f);
            o1.w = fmaxf(acc[7][j] * scv[7] + bv[7], 0.f);
            *(float4*)&sBuf[sp_idx(ls, (te << 3))]     = o0;
            *(float4*)&sBuf[sp_idx(ls, (te << 3) + 4)] = o1;
        }
    }

    // Wait for all mask blocks (they finish long before the K-loop does).
    if (tid == 0) {
        while (*(volatile int*)&g_ctr < 512) __nanosleep(100);
    }
    __syncthreads();
    __threadfence();

    // Load this block's mask tile [32 n][64 s]
    for (int i = tid; i < NN * 64; i += 256)
        smr[i >> 6][i & 63] = g_mr[(size_t)(b * NN + (i >> 6)) * SS + s0 + (i & 63)];
    __syncthreads();

    // GEMM2: obj_partial[n][e] = sum_ls smr[n][ls] * proj[ls][e]
    // 256 threads: tn = tid>>4 (2 n-rows each), tc = tid&15 (4 e each)
    {
        const int tn = tid >> 4;          // 0..15 -> n rows 2tn, 2tn+1
        const int tc = tid & 15;          // e0 = 4*tc
        float ob[2][4];
        #pragma unroll
        for (int r = 0; r < 2; r++)
            #pragma unroll
            for (int c = 0; c < 4; c++) ob[r][c] = 0.f;

        #pragma unroll 4
        for (int ls = 0; ls < 64; ls++) {
            float4 pv = *(const float4*)&sBuf[sp_idx(ls, tc << 2)];
            #pragma unroll
            for (int r = 0; r < 2; r++) {
                const float m = smr[(tn << 1) + r][ls];
                ob[r][0] += m * pv.x;
                ob[r][1] += m * pv.y;
                ob[r][2] += m * pv.z;
                ob[r][3] += m * pv.w;
            }
        }
        #pragma unroll
        for (int r = 0; r < 2; r++) {
            float* dst = &g_obj[(size_t)(b * NN + (tn << 1) + r) * EE
                                + eBase + (tc << 2)];
            #pragma unroll
            for (int c = 0; c < 4; c++)
                atomicAdd(dst + c, ob[r][c]);
        }
    }
}

// ---------------------------------------------------------------------------
// Kernel B: obj normalize + 2-layer MLP. Grid 128 = (b, ngroup of 4),
// 512 threads: tid = part*128 + e; part splits the 128-k reduction 4 ways.
// Also restores zeroed scratch state for graph replay.
// ---------------------------------------------------------------------------
__global__ void __launch_bounds__(512) kernelB(
    const float* __restrict__ b1, const float* __restrict__ b2,
    float* __restrict__ out)
{
    const int b  = blockIdx.x >> 3;
    const int ng = blockIdx.x & 7;
    const int n0 = ng * 4;
    const int tid  = threadIdx.x;
    const int e    = tid & 127;
    const int part = tid >> 7;           // 0..3

    __shared__ float px[4][4][EE];       // partials [part][row][e]
    __shared__ float xs[4][EE];
    __shared__ float hs[4][EE];
    __shared__ float inv[4];

    if (tid < 4) inv[tid] = g_minv[b * NN + n0 + tid];
    __syncthreads();
    {
        const size_t idx = (size_t)(b * NN + n0 + part) * EE + e;
        xs[part][e] = g_obj[idx] * inv[part];
        g_obj[idx] = 0.f;                 // restore for next graph replay
    }
    if (blockIdx.x == 0 && tid == 0) g_ctr = 0;
    __syncthreads();

    // layer 1 partials over k-quarter (coalesced w1T reads)
    {
        float h0 = 0.f, h1 = 0.f, h2 = 0.f, h3 = 0.f;
        const float* wt = g_w1T + (size_t)(part * 32) * EE + e;
        #pragma unroll 8
        for (int kk = 0; kk < 32; kk++) {
            const float wv = wt[(size_t)kk * EE];
            const int k = part * 32 + kk;
            h0 += wv * xs[0][k];
            h1 += wv * xs[1][k];
            h2 += wv * xs[2][k];
            h3 += wv * xs[3][k];
        }
        px[part][0][e] = h0;
        px[part][1][e] = h1;
        px[part][2][e] = h2;
        px[part][3][e] = h3;
    }
    __syncthreads();

    hs[part][e] = fmaxf(px[0][part][e] + px[1][part][e] + px[2][part][e]
                        + px[3][part][e] + b1[e], 0.f);
    __syncthreads();

    // layer 2 partials
    {
        float h0 = 0.f, h1 = 0.f, h2 = 0.f, h3 = 0.f;
        const float* wt = g_w2T + (size_t)(part * 32) * EE + e;
        #pragma unroll 8
        for (int kk = 0; kk < 32; kk++) {
            const float wv = wt[(size_t)kk * EE];
            const int k = part * 32 + kk;
            h0 += wv * hs[0][k];
            h1 += wv * hs[1][k];
            h2 += wv * hs[2][k];
            h3 += wv * hs[3][k];
        }
        px[part][0][e] = h0;
        px[part][1][e] = h1;
        px[part][2][e] = h2;
        px[part][3][e] = h3;
    }
    __syncthreads();

    out[((size_t)(b * NN + n0 + part)) * EE + e] =
        px[0][part][e] + px[1][part][e] + px[2][part][e] + px[3][part][e] + b2[e];
}

extern "C" void kernel_launch(void* const* d_in, const int* in_sizes, int n_in,
                              void* d_out, int out_size)
{
    const float* features = (const float*)d_in[0];
    const float* masks    = (const float*)d_in[1];
    const float* conv_w   = (const float*)d_in[2];
    const float* conv_b   = (const float*)d_in[3];
    const float* bn_gamma = (const float*)d_in[4];
    const float* bn_beta  = (const float*)d_in[5];
    const float* bn_mean  = (const float*)d_in[6];
    const float* bn_var   = (const float*)d_in[7];
    const float* w1       = (const float*)d_in[8];
    const float* b1       = (const float*)d_in[9];
    const float* w2       = (const float*)d_in[10];
    const float* b2       = (const float*)d_in[11];
    float* out = (float*)d_out;

    kernelA<<<642, 256>>>(features, masks, conv_w, conv_b,
                          bn_gamma, bn_beta, bn_mean, bn_var, w1, w2);
    kernelB<<<128, 512>>>(b1, b2, out);
}